// round 1
// baseline (speedup 1.0000x reference)
#include <cuda_runtime.h>
#include <cuda_bf16.h>
#include <math.h>

#define N_NODES 8192
#define EMBED   64
#define HID0    256
#define HID1    256
#define HID2    128
#define ACTION  8192
#define IN_SIZE (N_NODES + EMBED)   // 8256

// ---- scratch (__device__ globals; no allocation allowed) ----
__device__ float g_x[N_NODES];     // diagonal of state
__device__ float g_s[N_NODES];     // s = adj @ x
__device__ float g_t[HID0];        // t_j = adj[start,:] @ relu(s*w_j + b_j)
__device__ float g_emb[EMBED];     // log_softmax row
__device__ float g_y1[HID0];
__device__ float g_y3[HID2];

__device__ __forceinline__ float block_reduce_sum(float v) {
    __shared__ float sh[32];
    int lane = threadIdx.x & 31;
    int wid  = threadIdx.x >> 5;
    #pragma unroll
    for (int o = 16; o; o >>= 1) v += __shfl_down_sync(0xffffffffu, v, o);
    if (lane == 0) sh[wid] = v;
    __syncthreads();
    int nw = blockDim.x >> 5;
    v = (threadIdx.x < nw) ? sh[threadIdx.x] : 0.0f;
    if (wid == 0) {
        #pragma unroll
        for (int o = 16; o; o >>= 1) v += __shfl_down_sync(0xffffffffu, v, o);
    }
    return v;  // valid in thread 0
}

// K1: extract diagonal
__global__ void k_diag(const float* __restrict__ state) {
    int i = blockIdx.x * blockDim.x + threadIdx.x;
    if (i < N_NODES) g_x[i] = state[(size_t)i * (N_NODES + 1)];
}

// K2: s[i] = dot(state[i,:], x) - x[i]^2   (the 256 MB pass)
__global__ void __launch_bounds__(256) k_matvec(const float* __restrict__ state) {
    int i = blockIdx.x;
    const float4* __restrict__ rp = (const float4*)(state + (size_t)i * N_NODES);
    const float4* __restrict__ xp = (const float4*)g_x;
    float acc = 0.0f;
    #pragma unroll 8
    for (int j = threadIdx.x; j < N_NODES / 4; j += 256) {
        float4 a = rp[j];
        float4 b = xp[j];
        acc += a.x * b.x + a.y * b.y + a.z * b.z + a.w * b.w;
    }
    float tot = block_reduce_sum(acc);
    if (threadIdx.x == 0) {
        float xi = g_x[i];
        g_s[i] = tot - xi * xi;
    }
}

// K3: t[j] = sum_{i != start} state[start,i] * relu(s[i]*w[j] + b[j])
__global__ void __launch_bounds__(256) k_t(const float* __restrict__ state,
                                           const int* __restrict__ start_p,
                                           const float* __restrict__ gc1_w,
                                           const float* __restrict__ gc1_b) {
    int j = blockIdx.x;
    int st = *start_p;
    float wj = gc1_w[j];
    float bj = gc1_b[j];
    const float* __restrict__ row = state + (size_t)st * N_NODES;
    float acc = 0.0f;
    for (int i = threadIdx.x; i < N_NODES; i += 256) {
        float a = (i == st) ? 0.0f : row[i];
        acc += a * fmaxf(fmaf(g_s[i], wj, bj), 0.0f);
    }
    float tot = block_reduce_sum(acc);
    if (threadIdx.x == 0) g_t[j] = tot;
}

// K4: u = t @ gc2_w + gc2_b; h = relu(u); emb = log_softmax(h)   (64 threads)
__global__ void k_emb(const float* __restrict__ gc2_w,
                      const float* __restrict__ gc2_b) {
    __shared__ float sh[EMBED];
    __shared__ float lse;
    int c = threadIdx.x;  // 0..63
    float u = gc2_b[c];
    #pragma unroll 8
    for (int j = 0; j < HID0; j++) u = fmaf(g_t[j], gc2_w[j * EMBED + c], u);
    float h = fmaxf(u, 0.0f);
    sh[c] = h;
    __syncthreads();
    if (c == 0) {
        float m = sh[0];
        for (int i = 1; i < EMBED; i++) m = fmaxf(m, sh[i]);
        float s = 0.0f;
        for (int i = 0; i < EMBED; i++) s += expf(sh[i] - m);
        lse = m + logf(s);
    }
    __syncthreads();
    g_emb[c] = h - lse;
}

// K5: y1[r] = relu(fc1_w[r,:] . [state[start,:], emb] + fc1_b[r])
__global__ void __launch_bounds__(256) k_fc1(const float* __restrict__ state,
                                             const int* __restrict__ start_p,
                                             const float* __restrict__ fc1_w,
                                             const float* __restrict__ fc1_b) {
    int r = blockIdx.x;
    int st = *start_p;
    const float* __restrict__ wrow = fc1_w + (size_t)r * IN_SIZE;
    const float4* __restrict__ w4 = (const float4*)wrow;
    const float4* __restrict__ s4 = (const float4*)(state + (size_t)st * N_NODES);
    float acc = 0.0f;
    #pragma unroll 8
    for (int j = threadIdx.x; j < N_NODES / 4; j += 256) {
        float4 a = w4[j];
        float4 b = s4[j];
        acc += a.x * b.x + a.y * b.y + a.z * b.z + a.w * b.w;
    }
    if (threadIdx.x < EMBED)
        acc += wrow[N_NODES + threadIdx.x] * g_emb[threadIdx.x];
    float tot = block_reduce_sum(acc);
    if (threadIdx.x == 0) g_y1[r] = fmaxf(tot + fc1_b[r], 0.0f);
}

// K6: fc2 + fc3 in one block of 256 threads
__global__ void __launch_bounds__(256) k_fc23(const float* __restrict__ fc2_w,
                                              const float* __restrict__ fc2_b,
                                              const float* __restrict__ fc3_w,
                                              const float* __restrict__ fc3_b) {
    __shared__ float y1s[HID0];
    __shared__ float y2s[HID1];
    int t = threadIdx.x;
    y1s[t] = g_y1[t];
    __syncthreads();
    {
        const float* __restrict__ w = fc2_w + (size_t)t * HID0;
        float a0 = 0.f, a1 = 0.f, a2 = 0.f, a3 = 0.f;
        #pragma unroll 4
        for (int k = 0; k < HID0; k += 4) {
            a0 = fmaf(w[k + 0], y1s[k + 0], a0);
            a1 = fmaf(w[k + 1], y1s[k + 1], a1);
            a2 = fmaf(w[k + 2], y1s[k + 2], a2);
            a3 = fmaf(w[k + 3], y1s[k + 3], a3);
        }
        y2s[t] = fmaxf((a0 + a1) + (a2 + a3) + fc2_b[t], 0.0f);
    }
    __syncthreads();
    if (t < HID2) {
        const float* __restrict__ w = fc3_w + (size_t)t * HID1;
        float a0 = 0.f, a1 = 0.f, a2 = 0.f, a3 = 0.f;
        #pragma unroll 4
        for (int k = 0; k < HID1; k += 4) {
            a0 = fmaf(w[k + 0], y2s[k + 0], a0);
            a1 = fmaf(w[k + 1], y2s[k + 1], a1);
            a2 = fmaf(w[k + 2], y2s[k + 2], a2);
            a3 = fmaf(w[k + 3], y2s[k + 3], a3);
        }
        g_y3[t] = fmaxf((a0 + a1) + (a2 + a3) + fc3_b[t], 0.0f);
    }
}

// K7: out[a] = relu(fc4_w[a,:] . y3 + fc4_b[a]); one warp per output
__global__ void __launch_bounds__(256) k_fc4(const float* __restrict__ fc4_w,
                                             const float* __restrict__ fc4_b,
                                             float* __restrict__ out) {
    __shared__ float y3s[HID2];
    int tid = threadIdx.x;
    if (tid < HID2) y3s[tid] = g_y3[tid];
    __syncthreads();
    int warp = tid >> 5, lane = tid & 31;
    int a = blockIdx.x * 8 + warp;
    const float4* __restrict__ w4 = (const float4*)(fc4_w + (size_t)a * HID2);
    float4 w = w4[lane];
    float acc = w.x * y3s[lane * 4 + 0] + w.y * y3s[lane * 4 + 1] +
                w.z * y3s[lane * 4 + 2] + w.w * y3s[lane * 4 + 3];
    #pragma unroll
    for (int o = 16; o; o >>= 1) acc += __shfl_down_sync(0xffffffffu, acc, o);
    if (lane == 0) out[a] = fmaxf(acc + fc4_b[a], 0.0f);
}

extern "C" void kernel_launch(void* const* d_in, const int* in_sizes, int n_in,
                              void* d_out, int out_size) {
    const float* state = (const float*)d_in[0];
    const int*   start = (const int*)d_in[1];
    const float* gc1_w = (const float*)d_in[2];
    const float* gc1_b = (const float*)d_in[3];
    const float* gc2_w = (const float*)d_in[4];
    const float* gc2_b = (const float*)d_in[5];
    const float* fc1_w = (const float*)d_in[6];
    const float* fc1_b = (const float*)d_in[7];
    const float* fc2_w = (const float*)d_in[8];
    const float* fc2_b = (const float*)d_in[9];
    const float* fc3_w = (const float*)d_in[10];
    const float* fc3_b = (const float*)d_in[11];
    const float* fc4_w = (const float*)d_in[12];
    const float* fc4_b = (const float*)d_in[13];
    float* out = (float*)d_out;

    k_diag<<<N_NODES / 256, 256>>>(state);
    k_matvec<<<N_NODES, 256>>>(state);
    k_t<<<HID0, 256>>>(state, start, gc1_w, gc1_b);
    k_emb<<<1, EMBED>>>(gc2_w, gc2_b);
    k_fc1<<<HID0, 256>>>(state, start, fc1_w, fc1_b);
    k_fc23<<<1, 256>>>(fc2_w, fc2_b, fc3_w, fc3_b);
    k_fc4<<<ACTION / 8, 256>>>(fc4_w, fc4_b, out);
}

// round 2
// speedup vs baseline: 1.7650x; 1.7650x over previous
#include <cuda_runtime.h>
#include <cuda_bf16.h>
#include <math.h>

#define N_NODES 8192
#define EMBED   64
#define HID0    256
#define HID1    256
#define HID2    128
#define ACTION  8192
#define IN_SIZE (N_NODES + EMBED)   // 8256
#define RPB 8                       // rows per block in matvec

// ---- scratch (__device__ globals; no allocation allowed) ----
__device__ float g_x[N_NODES];     // diagonal of state
__device__ float g_s[N_NODES];     // s = adj @ x
__device__ float g_t[HID0];
__device__ float g_emb[EMBED];
__device__ float g_y1[HID0];
__device__ float g_y2[HID1];
__device__ float g_y3[HID2];

__device__ __forceinline__ float block_reduce_sum(float v) {
    __shared__ float sh[32];
    int lane = threadIdx.x & 31;
    int wid  = threadIdx.x >> 5;
    #pragma unroll
    for (int o = 16; o; o >>= 1) v += __shfl_down_sync(0xffffffffu, v, o);
    if (lane == 0) sh[wid] = v;
    __syncthreads();
    int nw = blockDim.x >> 5;
    v = (threadIdx.x < nw) ? sh[threadIdx.x] : 0.0f;
    if (wid == 0) {
        #pragma unroll
        for (int o = 16; o; o >>= 1) v += __shfl_down_sync(0xffffffffu, v, o);
    }
    return v;  // valid in thread 0
}

// K1: extract diagonal
__global__ void k_diag(const float* __restrict__ state) {
    int i = blockIdx.x * blockDim.x + threadIdx.x;
    if (i < N_NODES) g_x[i] = state[(size_t)i * (N_NODES + 1)];
}

// K2: s[i] = dot(state[i,:], x) - x[i]^2   (the 256 MB pass)
// 8 rows per block: x element read once per block -> L2 traffic 32MB not 256MB.
__global__ void __launch_bounds__(256) k_matvec(const float* __restrict__ state) {
    int r0 = blockIdx.x * RPB;
    const float4* __restrict__ base = (const float4*)(state + (size_t)r0 * N_NODES);
    const float4* __restrict__ xp = (const float4*)g_x;
    float acc[RPB];
    #pragma unroll
    for (int r = 0; r < RPB; r++) acc[r] = 0.0f;

    for (int j = threadIdx.x; j < N_NODES / 4; j += 256) {
        float4 xv = xp[j];
        #pragma unroll
        for (int r = 0; r < RPB; r++) {
            float4 a = base[(size_t)r * (N_NODES / 4) + j];
            acc[r] += a.x * xv.x + a.y * xv.y + a.z * xv.z + a.w * xv.w;
        }
    }
    // reduce RPB accumulators
    int lane = threadIdx.x & 31, wid = threadIdx.x >> 5;
    #pragma unroll
    for (int r = 0; r < RPB; r++)
        #pragma unroll
        for (int o = 16; o; o >>= 1) acc[r] += __shfl_down_sync(0xffffffffu, acc[r], o);
    __shared__ float sh[RPB][8];
    if (lane == 0) {
        #pragma unroll
        for (int r = 0; r < RPB; r++) sh[r][wid] = acc[r];
    }
    __syncthreads();
    if (threadIdx.x < RPB * 8) {
        int r = threadIdx.x >> 3, w = threadIdx.x & 7;
        float v = sh[r][w];
        v += __shfl_down_sync(0xffffffffu, v, 4, 8);
        v += __shfl_down_sync(0xffffffffu, v, 2, 8);
        v += __shfl_down_sync(0xffffffffu, v, 1, 8);
        if (w == 0) {
            int row = r0 + r;
            float xi = g_x[row];
            g_s[row] = v - xi * xi;
        }
    }
}

// K3: t[j] = sum_{i != start} state[start,i] * relu(s[i]*w[j] + b[j])
// 4 outputs per block, 64 blocks.
__global__ void __launch_bounds__(256) k_t(const float* __restrict__ state,
                                           const int* __restrict__ start_p,
                                           const float* __restrict__ gc1_w,
                                           const float* __restrict__ gc1_b) {
    int j0 = blockIdx.x * 4;
    int st = *start_p;
    float w0 = gc1_w[j0], w1 = gc1_w[j0 + 1], w2 = gc1_w[j0 + 2], w3 = gc1_w[j0 + 3];
    float b0 = gc1_b[j0], b1 = gc1_b[j0 + 1], b2 = gc1_b[j0 + 2], b3 = gc1_b[j0 + 3];
    const float* __restrict__ row = state + (size_t)st * N_NODES;
    float a0 = 0.f, a1 = 0.f, a2 = 0.f, a3 = 0.f;
    for (int i = threadIdx.x; i < N_NODES; i += 256) {
        float a = (i == st) ? 0.0f : row[i];
        float s = g_s[i];
        a0 += a * fmaxf(fmaf(s, w0, b0), 0.0f);
        a1 += a * fmaxf(fmaf(s, w1, b1), 0.0f);
        a2 += a * fmaxf(fmaf(s, w2, b2), 0.0f);
        a3 += a * fmaxf(fmaf(s, w3, b3), 0.0f);
    }
    float acc[4] = {a0, a1, a2, a3};
    int lane = threadIdx.x & 31, wid = threadIdx.x >> 5;
    #pragma unroll
    for (int r = 0; r < 4; r++)
        #pragma unroll
        for (int o = 16; o; o >>= 1) acc[r] += __shfl_down_sync(0xffffffffu, acc[r], o);
    __shared__ float sh[4][8];
    if (lane == 0) {
        #pragma unroll
        for (int r = 0; r < 4; r++) sh[r][wid] = acc[r];
    }
    __syncthreads();
    if (threadIdx.x < 32) {
        int r = threadIdx.x >> 3, w = threadIdx.x & 7;
        float v = sh[r][w];
        v += __shfl_down_sync(0xffffffffu, v, 4, 8);
        v += __shfl_down_sync(0xffffffffu, v, 2, 8);
        v += __shfl_down_sync(0xffffffffu, v, 1, 8);
        if (w == 0) g_t[j0 + r] = v;
    }
}

// K4: u = t @ gc2_w + gc2_b; h = relu(u); emb = log_softmax(h)
// 256 threads: (c = tid&63, p = tid>>6) -> 4 partial sums per column.
__global__ void __launch_bounds__(256) k_emb(const float* __restrict__ gc2_w,
                                             const float* __restrict__ gc2_b) {
    __shared__ float part[4][EMBED];
    __shared__ float hv[EMBED];
    __shared__ float red[2];
    int c = threadIdx.x & 63;
    int p = threadIdx.x >> 6;
    float u = 0.0f;
    #pragma unroll 8
    for (int j = p * 64; j < p * 64 + 64; j++)
        u = fmaf(g_t[j], gc2_w[j * EMBED + c], u);
    part[p][c] = u;
    __syncthreads();
    if (threadIdx.x < EMBED) {
        float h = part[0][c] + part[1][c] + part[2][c] + part[3][c] + gc2_b[c];
        hv[c] = fmaxf(h, 0.0f);
    }
    __syncthreads();
    if (threadIdx.x < 32) {
        float m = fmaxf(hv[threadIdx.x], hv[threadIdx.x + 32]);
        #pragma unroll
        for (int o = 16; o; o >>= 1) m = fmaxf(m, __shfl_xor_sync(0xffffffffu, m, o));
        float s = expf(hv[threadIdx.x] - m) + expf(hv[threadIdx.x + 32] - m);
        #pragma unroll
        for (int o = 16; o; o >>= 1) s += __shfl_xor_sync(0xffffffffu, s, o);
        if (threadIdx.x == 0) { red[0] = m + logf(s); }
    }
    __syncthreads();
    if (threadIdx.x < EMBED) g_emb[c] = hv[c] - red[0];
}

// K5: y1[r] = relu(fc1_w[r,:] . [state[start,:], emb] + fc1_b[r])
__global__ void __launch_bounds__(256) k_fc1(const float* __restrict__ state,
                                             const int* __restrict__ start_p,
                                             const float* __restrict__ fc1_w,
                                             const float* __restrict__ fc1_b) {
    int r = blockIdx.x;
    int st = *start_p;
    const float* __restrict__ wrow = fc1_w + (size_t)r * IN_SIZE;
    const float4* __restrict__ w4 = (const float4*)wrow;
    const float4* __restrict__ s4 = (const float4*)(state + (size_t)st * N_NODES);
    float acc = 0.0f;
    #pragma unroll 8
    for (int j = threadIdx.x; j < N_NODES / 4; j += 256) {
        float4 a = w4[j];
        float4 b = s4[j];
        acc += a.x * b.x + a.y * b.y + a.z * b.z + a.w * b.w;
    }
    if (threadIdx.x < EMBED)
        acc += wrow[N_NODES + threadIdx.x] * g_emb[threadIdx.x];
    float tot = block_reduce_sum(acc);
    if (threadIdx.x == 0) g_y1[r] = fmaxf(tot + fc1_b[r], 0.0f);
}

// K6: fc2, warp per output. 32 blocks x 8 warps = 256 outputs.
__global__ void __launch_bounds__(256) k_fc2(const float* __restrict__ fc2_w,
                                             const float* __restrict__ fc2_b) {
    int warp = threadIdx.x >> 5, lane = threadIdx.x & 31;
    int o = blockIdx.x * 8 + warp;
    const float4* __restrict__ w4 = (const float4*)(fc2_w + (size_t)o * HID0);
    const float4* __restrict__ y4 = (const float4*)g_y1;
    float acc = 0.0f;
    #pragma unroll
    for (int k = lane; k < HID0 / 4; k += 32) {
        float4 w = w4[k];
        float4 y = y4[k];
        acc += w.x * y.x + w.y * y.y + w.z * y.z + w.w * y.w;
    }
    #pragma unroll
    for (int off = 16; off; off >>= 1) acc += __shfl_down_sync(0xffffffffu, acc, off);
    if (lane == 0) g_y2[o] = fmaxf(acc + fc2_b[o], 0.0f);
}

// K7: fc3, warp per output. 16 blocks x 8 warps = 128 outputs.
__global__ void __launch_bounds__(256) k_fc3(const float* __restrict__ fc3_w,
                                             const float* __restrict__ fc3_b) {
    int warp = threadIdx.x >> 5, lane = threadIdx.x & 31;
    int o = blockIdx.x * 8 + warp;
    const float4* __restrict__ w4 = (const float4*)(fc3_w + (size_t)o * HID1);
    const float4* __restrict__ y4 = (const float4*)g_y2;
    float acc = 0.0f;
    #pragma unroll
    for (int k = lane; k < HID1 / 4; k += 32) {
        float4 w = w4[k];
        float4 y = y4[k];
        acc += w.x * y.x + w.y * y.y + w.z * y.z + w.w * y.w;
    }
    #pragma unroll
    for (int off = 16; off; off >>= 1) acc += __shfl_down_sync(0xffffffffu, acc, off);
    if (lane == 0) g_y3[o] = fmaxf(acc + fc3_b[o], 0.0f);
}

// K8: out[a] = relu(fc4_w[a,:] . y3 + fc4_b[a]); one warp per output
__global__ void __launch_bounds__(256) k_fc4(const float* __restrict__ fc4_w,
                                             const float* __restrict__ fc4_b,
                                             float* __restrict__ out) {
    __shared__ float y3s[HID2];
    int tid = threadIdx.x;
    if (tid < HID2) y3s[tid] = g_y3[tid];
    __syncthreads();
    int warp = tid >> 5, lane = tid & 31;
    int a = blockIdx.x * 8 + warp;
    const float4* __restrict__ w4 = (const float4*)(fc4_w + (size_t)a * HID2);
    float4 w = w4[lane];
    float acc = w.x * y3s[lane * 4 + 0] + w.y * y3s[lane * 4 + 1] +
                w.z * y3s[lane * 4 + 2] + w.w * y3s[lane * 4 + 3];
    #pragma unroll
    for (int o = 16; o; o >>= 1) acc += __shfl_down_sync(0xffffffffu, acc, o);
    if (lane == 0) out[a] = fmaxf(acc + fc4_b[a], 0.0f);
}

extern "C" void kernel_launch(void* const* d_in, const int* in_sizes, int n_in,
                              void* d_out, int out_size) {
    const float* state = (const float*)d_in[0];
    const int*   start = (const int*)d_in[1];
    const float* gc1_w = (const float*)d_in[2];
    const float* gc1_b = (const float*)d_in[3];
    const float* gc2_w = (const float*)d_in[4];
    const float* gc2_b = (const float*)d_in[5];
    const float* fc1_w = (const float*)d_in[6];
    const float* fc1_b = (const float*)d_in[7];
    const float* fc2_w = (const float*)d_in[8];
    const float* fc2_b = (const float*)d_in[9];
    const float* fc3_w = (const float*)d_in[10];
    const float* fc3_b = (const float*)d_in[11];
    const float* fc4_w = (const float*)d_in[12];
    const float* fc4_b = (const float*)d_in[13];
    float* out = (float*)d_out;

    k_diag<<<N_NODES / 256, 256>>>(state);
    k_matvec<<<N_NODES / RPB, 256>>>(state);
    k_t<<<HID0 / 4, 256>>>(state, start, gc1_w, gc1_b);
    k_emb<<<1, 256>>>(gc2_w, gc2_b);
    k_fc1<<<HID0, 256>>>(state, start, fc1_w, fc1_b);
    k_fc2<<<HID1 / 8, 256>>>(fc2_w, fc2_b);
    k_fc3<<<HID2 / 8, 256>>>(fc3_w, fc3_b);
    k_fc4<<<ACTION / 8, 256>>>(fc4_w, fc4_b, out);
}